// round 8
// baseline (speedup 1.0000x reference)
#include <cuda_runtime.h>
#include <cuda_bf16.h>
#include <cstdint>

// Problem constants (fixed shapes for NTXent_678604833492)
#define BATCH 4096
#define NROWS 8192          // 2*BATCH
#define DIMK  128
#define NTILE 64            // NROWS / 128
#define NPAIR 2080          // NTILE*(NTILE+1)/2 upper-triangle tiles

// Scratch (__device__ globals; allocation-free rule)
__device__ __nv_bfloat16 g_zbf[NROWS * DIMK];        // normalized bf16, row-major (2 MB)
__device__ float g_part[NTILE * NROWS];              // per-coltile row sumexp (2 MB)
__device__ float g_pos[NROWS];                       // positive cos per row
__device__ float g_blockpart[32];
__device__ unsigned g_cnt;                           // zero-init; self-resets

// ---------------------------------------------------------------------------
// helpers
// ---------------------------------------------------------------------------
__device__ __forceinline__ float ex2_approx(float x) {
    float r; asm("ex2.approx.ftz.f32 %0, %1;" : "=f"(r) : "f"(x)); return r;
}
__device__ __forceinline__ float lg2_approx(float x) {
    float r; asm("lg2.approx.f32 %0, %1;" : "=f"(r) : "f"(x)); return r;
}
__device__ __forceinline__ uint32_t smem_u32(const void* p) {
    uint32_t a;
    asm("{ .reg .u64 t; cvta.to.shared.u64 t, %1; cvt.u32.u64 %0, t; }" : "=r"(a) : "l"(p));
    return a;
}
__device__ __forceinline__ void ldsm_x4(uint32_t addr, uint32_t* r) {
    asm volatile("ldmatrix.sync.aligned.m8n8.x4.shared.b16 {%0,%1,%2,%3}, [%4];"
                 : "=r"(r[0]), "=r"(r[1]), "=r"(r[2]), "=r"(r[3]) : "r"(addr));
}
__device__ __forceinline__ void mma16816(float* d, const uint32_t* a, uint32_t b0, uint32_t b1) {
    asm volatile(
        "mma.sync.aligned.m16n8k16.row.col.f32.bf16.bf16.f32 "
        "{%0,%1,%2,%3}, {%4,%5,%6,%7}, {%8,%9}, {%0,%1,%2,%3};"
        : "+f"(d[0]), "+f"(d[1]), "+f"(d[2]), "+f"(d[3])
        : "r"(a[0]), "r"(a[1]), "r"(a[2]), "r"(a[3]), "r"(b0), "r"(b1));
}

// smem tile addressing: row-major 128 rows x 256B, 16B chunk XOR-swizzled by row&7
__device__ __forceinline__ uint32_t swz(int row, int kchunk /*16B units*/) {
    return ((uint32_t)row << 8) + (uint32_t)((kchunk ^ (row & 7)) << 4);
}

// ---------------------------------------------------------------------------
// Kernel 1: normalize rows -> g_zbf (bf16 row-major).  One warp per row.
// ---------------------------------------------------------------------------
__global__ __launch_bounds__(256)
void k_normalize(const float* __restrict__ zx, const float* __restrict__ zy) {
    int warp = threadIdx.x >> 5;
    int lane = threadIdx.x & 31;
    int row  = blockIdx.x * 8 + warp;

    const float* src = (row < BATCH) ? (zx + (size_t)row * DIMK)
                                     : (zy + (size_t)(row - BATCH) * DIMK);
    float4 v = reinterpret_cast<const float4*>(src)[lane];
    float ss = v.x * v.x + v.y * v.y + v.z * v.z + v.w * v.w;
    #pragma unroll
    for (int off = 16; off > 0; off >>= 1)
        ss += __shfl_xor_sync(0xffffffffu, ss, off);
    float inv = 1.0f / fmaxf(sqrtf(ss), 1e-8f);

    __nv_bfloat162 p0 = __float22bfloat162_rn(make_float2(v.x * inv, v.y * inv));
    __nv_bfloat162 p1 = __float22bfloat162_rn(make_float2(v.z * inv, v.w * inv));
    uint32_t* dst = reinterpret_cast<uint32_t*>(g_zbf + (size_t)row * DIMK);
    dst[lane * 2]     = *reinterpret_cast<uint32_t*>(&p0);
    dst[lane * 2 + 1] = *reinterpret_cast<uint32_t*>(&p1);
}

// ---------------------------------------------------------------------------
// Kernel 2: symmetric 128x128x128 bf16 mma.sync tile (upper triangle only)
//   off-diag tile (bi<bj): row sums -> g_part[bj][...], col sums -> g_part[bi][...]
//   diag tile: row sums with diagonal masked.
//   tiles with bj-bi==32: capture positive cos into g_pos (both rows).
// ---------------------------------------------------------------------------
#define SMEM_SSUM 65536
#define SMEM_SCOL (65536 + 1024)
#define SMEM_TOT  (65536 + 1024 + 2048)

__global__ __launch_bounds__(256, 2)
void k_mma_tile() {
    extern __shared__ char smem[];
    const uint32_t sa = smem_u32(smem);
    float* ssum = reinterpret_cast<float*>(smem + SMEM_SSUM);   // [2][128]
    float* scol = reinterpret_cast<float*>(smem + SMEM_SCOL);   // [128][4]

    const int tid  = threadIdx.x;
    const int wid  = tid >> 5;
    const int lane = tid & 31;

    // decode upper-triangle pair (bi <= bj) from linear block id
    int t = blockIdx.x, bi = 0;
    while (t >= NTILE - bi) { t -= NTILE - bi; bi++; }
    const int bj = bi + t;
    const bool diag = (bi == bj);
    const bool posT = (bj - bi == 32);

    // cooperative tile load: row-major gmem -> swizzled smem
    const uint4* gA = reinterpret_cast<const uint4*>(g_zbf + (size_t)bi * 128 * DIMK);
    const uint4* gB = reinterpret_cast<const uint4*>(g_zbf + (size_t)bj * 128 * DIMK);
    #pragma unroll
    for (int i = 0; i < 8; i++) {
        int idx = tid + i * 256;            // 0..2047
        int row = idx >> 4, c = idx & 15;
        uint32_t off = swz(row, c);
        *reinterpret_cast<uint4*>(smem + off) = gA[idx];
        if (!diag)
            *reinterpret_cast<uint4*>(smem + 32768 + off) = gB[idx];
    }
    __syncthreads();
    const uint32_t sb = diag ? sa : (sa + 32768);

    // warp layout: 4 (M) x 2 (N); warp tile 32 x 64
    const int mw = wid & 3;
    const int arow0 = mw * 32;
    const int bcol0 = (wid >> 2) * 64;
    const int g  = lane >> 3;
    const int rr = lane & 7;

    float acc[2][8][4];
    #pragma unroll
    for (int mt = 0; mt < 2; mt++)
        #pragma unroll
        for (int nt = 0; nt < 8; nt++)
            #pragma unroll
            for (int q = 0; q < 4; q++) acc[mt][nt][q] = 0.0f;

    #pragma unroll
    for (int ks = 0; ks < 8; ks++) {
        const int kc = ks * 2;
        uint32_t afr[2][4], bfr[4][4];
        #pragma unroll
        for (int mt = 0; mt < 2; mt++) {
            uint32_t addr = sa + swz(arow0 + mt * 16 + rr + (g & 1) * 8, kc + (g >> 1));
            ldsm_x4(addr, afr[mt]);
        }
        #pragma unroll
        for (int nq = 0; nq < 4; nq++) {
            uint32_t addr = sb + swz(bcol0 + nq * 16 + (g >> 1) * 8 + rr, kc + (g & 1));
            ldsm_x4(addr, bfr[nq]);
        }
        #pragma unroll
        for (int mt = 0; mt < 2; mt++)
            #pragma unroll
            for (int nt = 0; nt < 8; nt++)
                mma16816(acc[mt][nt], afr[mt], bfr[nt >> 1][(nt & 1) * 2],
                         bfr[nt >> 1][(nt & 1) * 2 + 1]);
    }

    // epilogue: e = exp2((cos-1)*2*log2e); accumulate row sums and col sums
    const float CEXP = 2.8853900817779268f;   // 2 * log2(e)
    float cs[8][2];
    #pragma unroll
    for (int nt = 0; nt < 8; nt++) { cs[nt][0] = 0.0f; cs[nt][1] = 0.0f; }

    #pragma unroll
    for (int mt = 0; mt < 2; mt++) {
        #pragma unroll
        for (int rh = 0; rh < 2; rh++) {
            int lrow = arow0 + mt * 16 + (lane >> 2) + rh * 8;
            int grow = bi * 128 + lrow;
            float rs = 0.0f;
            #pragma unroll
            for (int nt = 0; nt < 8; nt++) {
                #pragma unroll
                for (int c = 0; c < 2; c++) {
                    float s = acc[mt][nt][rh * 2 + c];
                    int lcol = bcol0 + nt * 8 + (lane & 3) * 2 + c;
                    float e = ex2_approx((s - 1.0f) * CEXP);
                    if (diag && lrow == lcol) e = 0.0f;
                    if (posT && lrow == lcol) {           // positive pair capture
                        g_pos[grow] = s;
                        g_pos[bj * 128 + lcol] = s;
                    }
                    rs += e;
                    cs[nt][c] += e;
                }
            }
            rs += __shfl_xor_sync(0xffffffffu, rs, 1);
            rs += __shfl_xor_sync(0xffffffffu, rs, 2);
            if ((lane & 3) == 0) ssum[(wid >> 2) * 128 + lrow] = rs;
        }
    }

    if (!diag) {
        #pragma unroll
        for (int nt = 0; nt < 8; nt++) {
            #pragma unroll
            for (int c = 0; c < 2; c++) {
                float v = cs[nt][c];
                v += __shfl_xor_sync(0xffffffffu, v, 4);
                v += __shfl_xor_sync(0xffffffffu, v, 8);
                v += __shfl_xor_sync(0xffffffffu, v, 16);
                cs[nt][c] = v;
            }
        }
        if ((lane >> 2) == 0) {
            #pragma unroll
            for (int nt = 0; nt < 8; nt++)
                #pragma unroll
                for (int c = 0; c < 2; c++) {
                    int col = bcol0 + nt * 8 + (lane & 3) * 2 + c;
                    scol[col * 4 + mw] = cs[nt][c];
                }
        }
    }
    __syncthreads();

    if (tid < 128) {
        g_part[(size_t)bj * NROWS + bi * 128 + tid] = ssum[tid] + ssum[128 + tid];
        if (!diag) {
            float cv = scol[tid * 4] + scol[tid * 4 + 1]
                     + scol[tid * 4 + 2] + scol[tid * 4 + 3];
            g_part[(size_t)bi * NROWS + bj * 128 + tid] = cv;
        }
    }
}

// ---------------------------------------------------------------------------
// Kernel 3 (fused): per-row loss + full deterministic reduction -> out[0]
//   32 blocks x 256 threads; thread per row (coalesced g_part reads);
//   last-block pattern for the final 32-partial sum.
// ---------------------------------------------------------------------------
__global__ __launch_bounds__(256)
void k_loss(float* __restrict__ out) {
    __shared__ float s[256];
    __shared__ unsigned rank;
    const int tid = threadIdx.x;
    const int row = blockIdx.x * 256 + tid;

    float se = 0.0f;
    #pragma unroll 8
    for (int k = 0; k < NTILE; k++)
        se += g_part[(size_t)k * NROWS + row];

    float lnse = lg2_approx(se) * 0.6931471805599453f;
    float loss = 2.0f + lnse - 2.0f * g_pos[row];

    s[tid] = loss;
    __syncthreads();
    #pragma unroll
    for (int off = 128; off > 0; off >>= 1) {
        if (tid < off) s[tid] += s[tid + off];
        __syncthreads();
    }
    if (tid == 0) {
        g_blockpart[blockIdx.x] = s[0];
        __threadfence();
        rank = atomicAdd(&g_cnt, 1u);
    }
    __syncthreads();
    if (rank == 31 && tid < 32) {            // last block finishes
        float v = g_blockpart[tid];
        #pragma unroll
        for (int off = 16; off > 0; off >>= 1)
            v += __shfl_xor_sync(0xffffffffu, v, off);
        if (tid == 0) {
            out[0] = v / (float)NROWS;
            g_cnt = 0;                        // self-reset for next call
        }
    }
}

// ---------------------------------------------------------------------------
extern "C" void kernel_launch(void* const* d_in, const int* in_sizes, int n_in,
                              void* d_out, int out_size) {
    const float* zx = (const float*)d_in[0];
    const float* zy = (const float*)d_in[1];
    float* out = (float*)d_out;

    cudaFuncSetAttribute(k_mma_tile, cudaFuncAttributeMaxDynamicSharedMemorySize, SMEM_TOT);

    k_normalize<<<NROWS / 8, 256>>>(zx, zy);
    k_mma_tile<<<NPAIR, 256, SMEM_TOT>>>();
    k_loss<<<32, 256>>>(out);
}

// round 9
// speedup vs baseline: 1.0343x; 1.0343x over previous
#include <cuda_runtime.h>
#include <cuda_bf16.h>
#include <cstdint>

// Problem constants (fixed shapes for NTXent_678604833492)
#define BATCH 4096
#define NROWS 8192          // 2*BATCH
#define DIMK  128
#define NTILE 64            // NROWS / 128
#define NPAIR 2080          // NTILE*(NTILE+1)/2 upper-triangle tiles

// Scratch (__device__ globals; allocation-free rule)
__device__ __nv_bfloat16 g_zbf[NROWS * DIMK];        // normalized bf16, row-major (2 MB)
__device__ float g_part[NTILE * NROWS];              // per-coltile row sumexp (2 MB)
__device__ float g_pos[NROWS];                       // positive cos per row
__device__ float g_blockpart[32];
__device__ unsigned g_cnt;                           // zero-init; self-resets

// ---------------------------------------------------------------------------
// helpers
// ---------------------------------------------------------------------------
__device__ __forceinline__ float ex2_approx(float x) {
    float r; asm("ex2.approx.ftz.f32 %0, %1;" : "=f"(r) : "f"(x)); return r;
}
__device__ __forceinline__ float lg2_approx(float x) {
    float r; asm("lg2.approx.f32 %0, %1;" : "=f"(r) : "f"(x)); return r;
}
__device__ __forceinline__ uint32_t smem_u32(const void* p) {
    uint32_t a;
    asm("{ .reg .u64 t; cvta.to.shared.u64 t, %1; cvt.u32.u64 %0, t; }" : "=r"(a) : "l"(p));
    return a;
}
__device__ __forceinline__ void ldsm_x4(uint32_t addr, uint32_t* r) {
    asm volatile("ldmatrix.sync.aligned.m8n8.x4.shared.b16 {%0,%1,%2,%3}, [%4];"
                 : "=r"(r[0]), "=r"(r[1]), "=r"(r[2]), "=r"(r[3]) : "r"(addr));
}
__device__ __forceinline__ void mma16816(float* d, const uint32_t* a, uint32_t b0, uint32_t b1) {
    asm volatile(
        "mma.sync.aligned.m16n8k16.row.col.f32.bf16.bf16.f32 "
        "{%0,%1,%2,%3}, {%4,%5,%6,%7}, {%8,%9}, {%0,%1,%2,%3};"
        : "+f"(d[0]), "+f"(d[1]), "+f"(d[2]), "+f"(d[3])
        : "r"(a[0]), "r"(a[1]), "r"(a[2]), "r"(a[3]), "r"(b0), "r"(b1));
}

// smem tile addressing: row-major 128 rows x 256B, 16B chunk XOR-swizzled by row&7
__device__ __forceinline__ uint32_t swz(int row, int kchunk /*16B units*/) {
    return ((uint32_t)row << 8) + (uint32_t)((kchunk ^ (row & 7)) << 4);
}

// ---------------------------------------------------------------------------
// Kernel 1: normalize rows -> g_zbf (bf16 row-major).  One warp per row.
// ---------------------------------------------------------------------------
__global__ __launch_bounds__(256)
void k_normalize(const float* __restrict__ zx, const float* __restrict__ zy) {
    int warp = threadIdx.x >> 5;
    int lane = threadIdx.x & 31;
    int row  = blockIdx.x * 8 + warp;

    const float* src = (row < BATCH) ? (zx + (size_t)row * DIMK)
                                     : (zy + (size_t)(row - BATCH) * DIMK);
    float4 v = reinterpret_cast<const float4*>(src)[lane];
    float ss = v.x * v.x + v.y * v.y + v.z * v.z + v.w * v.w;
    #pragma unroll
    for (int off = 16; off > 0; off >>= 1)
        ss += __shfl_xor_sync(0xffffffffu, ss, off);
    float inv = 1.0f / fmaxf(sqrtf(ss), 1e-8f);

    __nv_bfloat162 p0 = __float22bfloat162_rn(make_float2(v.x * inv, v.y * inv));
    __nv_bfloat162 p1 = __float22bfloat162_rn(make_float2(v.z * inv, v.w * inv));
    uint32_t* dst = reinterpret_cast<uint32_t*>(g_zbf + (size_t)row * DIMK);
    dst[lane * 2]     = *reinterpret_cast<uint32_t*>(&p0);
    dst[lane * 2 + 1] = *reinterpret_cast<uint32_t*>(&p1);
}

// ---------------------------------------------------------------------------
// Kernel 2: symmetric 128x128x128 bf16 mma.sync tile (upper triangle only)
//   off-diag tile (bi<bj): row sums -> g_part[bj][...], col sums -> g_part[bi][...]
//   diag tile: row sums with diagonal masked.
//   tiles with bj-bi==32: capture positive cos into g_pos (both rows).
// ---------------------------------------------------------------------------
#define SMEM_SSUM 65536
#define SMEM_SCOL (65536 + 1024)
#define SMEM_TOT  (65536 + 1024 + 2048)

__global__ __launch_bounds__(256, 2)
void k_mma_tile() {
    extern __shared__ char smem[];
    const uint32_t sa = smem_u32(smem);
    float* ssum = reinterpret_cast<float*>(smem + SMEM_SSUM);   // [2][128]
    float* scol = reinterpret_cast<float*>(smem + SMEM_SCOL);   // [128][4]

    const int tid  = threadIdx.x;
    const int wid  = tid >> 5;
    const int lane = tid & 31;

    // decode upper-triangle pair (bi <= bj) from linear block id
    int t = blockIdx.x, bi = 0;
    while (t >= NTILE - bi) { t -= NTILE - bi; bi++; }
    const int bj = bi + t;
    const bool diag = (bi == bj);
    const bool posT = (bj - bi == 32);

    // cooperative tile load: row-major gmem -> swizzled smem
    const uint4* gA = reinterpret_cast<const uint4*>(g_zbf + (size_t)bi * 128 * DIMK);
    const uint4* gB = reinterpret_cast<const uint4*>(g_zbf + (size_t)bj * 128 * DIMK);
    #pragma unroll
    for (int i = 0; i < 8; i++) {
        int idx = tid + i * 256;            // 0..2047
        int row = idx >> 4, c = idx & 15;
        uint32_t off = swz(row, c);
        *reinterpret_cast<uint4*>(smem + off) = gA[idx];
        if (!diag)
            *reinterpret_cast<uint4*>(smem + 32768 + off) = gB[idx];
    }
    __syncthreads();
    const uint32_t sb = diag ? sa : (sa + 32768);

    // warp layout: 4 (M) x 2 (N); warp tile 32 x 64
    const int mw = wid & 3;
    const int arow0 = mw * 32;
    const int bcol0 = (wid >> 2) * 64;
    const int g  = lane >> 3;
    const int rr = lane & 7;

    float acc[2][8][4];
    #pragma unroll
    for (int mt = 0; mt < 2; mt++)
        #pragma unroll
        for (int nt = 0; nt < 8; nt++)
            #pragma unroll
            for (int q = 0; q < 4; q++) acc[mt][nt][q] = 0.0f;

    #pragma unroll
    for (int ks = 0; ks < 8; ks++) {
        const int kc = ks * 2;
        uint32_t afr[2][4], bfr[4][4];
        #pragma unroll
        for (int mt = 0; mt < 2; mt++) {
            uint32_t addr = sa + swz(arow0 + mt * 16 + rr + (g & 1) * 8, kc + (g >> 1));
            ldsm_x4(addr, afr[mt]);
        }
        #pragma unroll
        for (int nq = 0; nq < 4; nq++) {
            uint32_t addr = sb + swz(bcol0 + nq * 16 + (g >> 1) * 8 + rr, kc + (g & 1));
            ldsm_x4(addr, bfr[nq]);
        }
        #pragma unroll
        for (int mt = 0; mt < 2; mt++)
            #pragma unroll
            for (int nt = 0; nt < 8; nt++)
                mma16816(acc[mt][nt], afr[mt], bfr[nt >> 1][(nt & 1) * 2],
                         bfr[nt >> 1][(nt & 1) * 2 + 1]);
    }

    // epilogue: e = exp2((cos-1)*2*log2e); accumulate row sums and col sums
    const float CEXP = 2.8853900817779268f;   // 2 * log2(e)
    float cs[8][2];
    #pragma unroll
    for (int nt = 0; nt < 8; nt++) { cs[nt][0] = 0.0f; cs[nt][1] = 0.0f; }

    #pragma unroll
    for (int mt = 0; mt < 2; mt++) {
        #pragma unroll
        for (int rh = 0; rh < 2; rh++) {
            int lrow = arow0 + mt * 16 + (lane >> 2) + rh * 8;
            int grow = bi * 128 + lrow;
            float rs = 0.0f;
            #pragma unroll
            for (int nt = 0; nt < 8; nt++) {
                #pragma unroll
                for (int c = 0; c < 2; c++) {
                    float s = acc[mt][nt][rh * 2 + c];
                    int lcol = bcol0 + nt * 8 + (lane & 3) * 2 + c;
                    float e = ex2_approx((s - 1.0f) * CEXP);
                    if (diag && lrow == lcol) e = 0.0f;
                    if (posT && lrow == lcol) {           // positive pair capture
                        g_pos[grow] = s;
                        g_pos[bj * 128 + lcol] = s;
                    }
                    rs += e;
                    cs[nt][c] += e;
                }
            }
            rs += __shfl_xor_sync(0xffffffffu, rs, 1);
            rs += __shfl_xor_sync(0xffffffffu, rs, 2);
            if ((lane & 3) == 0) ssum[(wid >> 2) * 128 + lrow] = rs;
        }
    }

    if (!diag) {
        #pragma unroll
        for (int nt = 0; nt < 8; nt++) {
            #pragma unroll
            for (int c = 0; c < 2; c++) {
                float v = cs[nt][c];
                v += __shfl_xor_sync(0xffffffffu, v, 4);
                v += __shfl_xor_sync(0xffffffffu, v, 8);
                v += __shfl_xor_sync(0xffffffffu, v, 16);
                cs[nt][c] = v;
            }
        }
        if ((lane >> 2) == 0) {
            #pragma unroll
            for (int nt = 0; nt < 8; nt++)
                #pragma unroll
                for (int c = 0; c < 2; c++) {
                    int col = bcol0 + nt * 8 + (lane & 3) * 2 + c;
                    scol[col * 4 + mw] = cs[nt][c];
                }
        }
    }
    __syncthreads();

    if (tid < 128) {
        g_part[(size_t)bj * NROWS + bi * 128 + tid] = ssum[tid] + ssum[128 + tid];
        if (!diag) {
            float cv = scol[tid * 4] + scol[tid * 4 + 1]
                     + scol[tid * 4 + 2] + scol[tid * 4 + 3];
            g_part[(size_t)bi * NROWS + bj * 128 + tid] = cv;
        }
    }
}

// ---------------------------------------------------------------------------
// Kernel 3 (fused): per-row loss + full deterministic reduction -> out[0]
//   32 blocks x 256 threads; thread per row (coalesced g_part reads);
//   last-block pattern for the final 32-partial sum.
// ---------------------------------------------------------------------------
__global__ __launch_bounds__(256)
void k_loss(float* __restrict__ out) {
    __shared__ float s[256];
    __shared__ unsigned rank;
    const int tid = threadIdx.x;
    const int row = blockIdx.x * 256 + tid;

    float se = 0.0f;
    #pragma unroll 8
    for (int k = 0; k < NTILE; k++)
        se += g_part[(size_t)k * NROWS + row];

    float lnse = lg2_approx(se) * 0.6931471805599453f;
    float loss = 2.0f + lnse - 2.0f * g_pos[row];

    s[tid] = loss;
    __syncthreads();
    #pragma unroll
    for (int off = 128; off > 0; off >>= 1) {
        if (tid < off) s[tid] += s[tid + off];
        __syncthreads();
    }
    if (tid == 0) {
        g_blockpart[blockIdx.x] = s[0];
        __threadfence();
        rank = atomicAdd(&g_cnt, 1u);
    }
    __syncthreads();
    if (rank == 31 && tid < 32) {            // last block finishes
        float v = g_blockpart[tid];
        #pragma unroll
        for (int off = 16; off > 0; off >>= 1)
            v += __shfl_xor_sync(0xffffffffu, v, off);
        if (tid == 0) {
            out[0] = v / (float)NROWS;
            g_cnt = 0;                        // self-reset for next call
        }
    }
}

// ---------------------------------------------------------------------------
extern "C" void kernel_launch(void* const* d_in, const int* in_sizes, int n_in,
                              void* d_out, int out_size) {
    const float* zx = (const float*)d_in[0];
    const float* zy = (const float*)d_in[1];
    float* out = (float*)d_out;

    cudaFuncSetAttribute(k_mma_tile, cudaFuncAttributeMaxDynamicSharedMemorySize, SMEM_TOT);

    k_normalize<<<NROWS / 8, 256>>>(zx, zy);
    k_mma_tile<<<NPAIR, 256, SMEM_TOT>>>();
    k_loss<<<32, 256>>>(out);
}